// round 11
// baseline (speedup 1.0000x reference)
#include <cuda_runtime.h>
#include <cstdint>

// x:[4096,4096] f32, qweight:[4096,1376] i32 (8x int4 along O), scales:[32,11008] f32,
// qzeros:[32,1376] i32, out:[4096,11008] f32, group_size=128.
// fp16 mma.sync m16n8k16 GEMM (fp32 accum), ldmatrix fragments, 2 CTAs/SM.

#define I_DIM 4096
#define O_DIM 11008
#define OPACK 1376
#define BM 128
#define BN 128
#define BK 64
#define NITER 64
#define THREADS 256

#define A_WORDS (BM * BK / 2)             // 4096 words = 16KB image
#define B_WORDS (BN * BK / 2)             // 4096 words = 16KB
#define STAGE_WORDS (A_WORDS + B_WORDS)   // 8192
#define SMEM_BYTES (2 * STAGE_WORDS * 4)  // 65536

// x as fp16x2 tile images: [rt(32)][itk(64)][4096 words]
__device__ uint32_t g_xr[(size_t)32 * 64 * A_WORDS];

__device__ __forceinline__ uint32_t pack_f16x2(float lo, float hi) {
    uint32_t d;
    asm("cvt.rn.f16x2.f32 %0, %1, %2;" : "=r"(d) : "f"(hi), "f"(lo));
    return d;
}

__device__ __forceinline__ uint32_t smem_u32(const void* p) {
    uint32_t a;
    asm("{ .reg .u64 t; cvta.to.shared.u64 t, %1; cvt.u32.u64 %0, t; }" : "=r"(a) : "l"(p));
    return a;
}

__device__ __forceinline__ void cp_async16(uint32_t dst, const void* src) {
    asm volatile("cp.async.cg.shared.global [%0], [%1], 16;" :: "r"(dst), "l"(src) : "memory");
}

__device__ __forceinline__ void ldmatrix_x4(uint32_t* r, uint32_t addr) {
    asm volatile("ldmatrix.sync.aligned.m8n8.x4.shared.b16 {%0,%1,%2,%3}, [%4];"
                 : "=r"(r[0]), "=r"(r[1]), "=r"(r[2]), "=r"(r[3]) : "r"(addr));
}

__device__ __forceinline__ void mma_f16(float* d, const uint32_t* a, const uint32_t* b) {
    asm volatile(
        "mma.sync.aligned.m16n8k16.row.col.f32.f16.f16.f32 "
        "{%0,%1,%2,%3},{%4,%5,%6,%7},{%8,%9},{%0,%1,%2,%3};"
        : "+f"(d[0]), "+f"(d[1]), "+f"(d[2]), "+f"(d[3])
        : "r"(a[0]), "r"(a[1]), "r"(a[2]), "r"(a[3]), "r"(b[0]), "r"(b[1]));
}

// ---- pre-kernel: x -> fp16 tile images ----
// image word(r,k2) = r*32 + ((chunk ^ ta(r))<<2) + (k2&3), chunk=k2>>2,
// ta(r) = ((r>>1)&3) | ((r&1)<<2)
__global__ __launch_bounds__(256)
void round_x_kernel(const float4* __restrict__ x) {
    size_t idx = (size_t)blockIdx.x * 256 + threadIdx.x;   // over 8-float chunks
    int r  = (int)(idx >> 9);
    int cg = (int)(idx & 511);
    float4 v0 = x[idx * 2];
    float4 v1 = x[idx * 2 + 1];
    uint4 u;
    u.x = pack_f16x2(v0.x, v0.y);
    u.y = pack_f16x2(v0.z, v0.w);
    u.z = pack_f16x2(v1.x, v1.y);
    u.w = pack_f16x2(v1.z, v1.w);
    int rt = r >> 7, rl = r & 127;
    int itk = cg >> 3, c = cg & 7;
    int ta = ((rl >> 1) & 3) | ((rl & 1) << 2);
    *reinterpret_cast<uint4*>(
        g_xr + (((size_t)rt * 64 + itk) << 12) + rl * 32 + ((c ^ ta) << 2)) = u;
}

// ---- main GEMM ----
__global__ __launch_bounds__(THREADS, 2)
void q4_f16_mma(const int* __restrict__ qweight,
                const float* __restrict__ scales,
                const int* __restrict__ qzeros,
                float* __restrict__ out) {
    extern __shared__ uint32_t smem[];
    const uint32_t sbase = smem_u32(smem);

    const int tid  = threadIdx.x;
    const int lane = tid & 31;
    const int wid  = tid >> 5;
    const int gi   = lane >> 2;
    const int tq   = lane & 3;

    const int row0 = blockIdx.y * BM;
    const int col0 = blockIdx.x * BN;

    // 8 warps: 2 (M, 64) x 4 (N, 32)
    const int wm = wid & 1;
    const int wn = wid >> 1;

    // ldmatrix lane roles
    const int lj = lane & 7;
    const int lg = lane >> 3;
    const int ta_l = ((lj >> 1) & 3) | ((lj & 1) << 2);
    const int a_csel = lg >> 1;
    uint32_t a_row_byte[4];
#pragma unroll
    for (int mi = 0; mi < 4; mi++)
        a_row_byte[mi] = (uint32_t)(wm * 64 + mi * 16 + ((lg & 1) << 3) + lj) * 128;
    const int b_csel = lg & 1;
    uint32_t b_row_byte[2];
    int tb_l[2];
#pragma unroll
    for (int p = 0; p < 2; p++) {
        int nhi = wn * 4 + 2 * p + (lg >> 1);   // n>>3
        b_row_byte[p] = (uint32_t)(nhi * 8 + lj) * 128;
        tb_l[p] = ta_l ^ (nhi & 7);
    }

    // B loader: ow = qweight word col (0..15), kt8 = k-octet (0..7), oh = o-half
    const int ow  = tid & 15;
    const int kt8 = (tid >> 4) & 7;
    const int oh  = tid >> 7;
    const int*   qw_base = qweight + (col0 >> 3) + ow;
    const int*   qz_base = qzeros  + (col0 >> 3) + ow;
    const float* sc_base = scales  + col0 + ow * 8 + oh * 4;

    const uint32_t* a_img = g_xr + (((size_t)(row0 >> 7)) * 64 << 12);

    uint32_t wS[8];
    uint32_t zS;
    float4 sSv;

    float acc[4][4][4];
#pragma unroll
    for (int mi = 0; mi < 4; mi++)
#pragma unroll
        for (int nb = 0; nb < 4; nb++)
#pragma unroll
            for (int j = 0; j < 4; j++) acc[mi][nb][j] = 0.0f;

    auto issueA = [&](int it, int stage) {
        const uint32_t aB = sbase + stage * (STAGE_WORDS * 4);
        const uint32_t* src = a_img + ((size_t)it << 12);
#pragma unroll
        for (int j = 0; j < 4; j++) {
            int c = tid + j * 256;
            cp_async16(aB + c * 16, src + c * 4);
        }
        asm volatile("cp.async.commit_group;" ::: "memory");
    };

    auto loadB = [&](int it) {
        const int k0 = it * BK;
#pragma unroll
        for (int j = 0; j < 8; j++)
            wS[j] = (uint32_t)qw_base[(size_t)(k0 + kt8 * 8 + j) * OPACK];
        const int g = it >> 1;
        zS  = (uint32_t)qz_base[(size_t)g * OPACK];
        sSv = *reinterpret_cast<const float4*>(sc_base + (size_t)g * O_DIM);
    };

    // B image word(n,k2) = n*32 + ((chunk ^ tb(n))<<2) + (k2&3)
    // tb(n) = ta(n&7) ^ ((n>>3)&7); this thread: chunk = kt8, k2&3 = 0..3
    auto storeB = [&](int stage) {
        uint32_t* Bs = smem + stage * STAGE_WORDS + A_WORDS;
        float sc[4] = {sSv.x, sSv.y, sSv.z, sSv.w};
#pragma unroll
        for (int o4 = 0; o4 < 4; o4++) {
            int o = oh * 4 + o4;
            float fz = __uint_as_float(0x4B000000u | ((zS >> (4 * o)) & 0xF));
            float d[8];
#pragma unroll
            for (int j = 0; j < 8; j++) {
                float f = __uint_as_float(0x4B000000u | ((wS[j] >> (4 * o)) & 0xF));
                d[j] = (f - fz) * sc[o4];
            }
            uint4 u;
            u.x = pack_f16x2(d[0], d[1]);
            u.y = pack_f16x2(d[2], d[3]);
            u.z = pack_f16x2(d[4], d[5]);
            u.w = pack_f16x2(d[6], d[7]);
            int n  = ow * 8 + o;
            int tb = (((o >> 1) & 3) | ((o & 1) << 2)) ^ (ow & 7);
            *reinterpret_cast<uint4*>(Bs + n * 32 + ((kt8 ^ tb) << 2)) = u;
        }
    };

    auto compute = [&](int stage) {
        const uint32_t aB = sbase + stage * (STAGE_WORDS * 4);
        const uint32_t bB = aB + A_WORDS * 4;
#pragma unroll
        for (int kb = 0; kb < 4; kb++) {
            uint32_t a[4][4];
#pragma unroll
            for (int mi = 0; mi < 4; mi++)
                ldmatrix_x4(a[mi], aB + a_row_byte[mi]
                            + ((uint32_t)((2 * kb + a_csel) ^ ta_l) << 4));
            uint32_t b[2][4];
#pragma unroll
            for (int p = 0; p < 2; p++)
                ldmatrix_x4(b[p], bB + b_row_byte[p]
                            + ((uint32_t)((2 * kb + b_csel) ^ tb_l[p]) << 4));
#pragma unroll
            for (int mi = 0; mi < 4; mi++)
#pragma unroll
                for (int nb = 0; nb < 4; nb++)
                    mma_f16(acc[mi][nb], a[mi], &b[nb >> 1][(nb & 1) * 2]);
        }
    };

    // ---------------- pipeline ----------------
    issueA(0, 0);
    loadB(0);
    asm volatile("cp.async.wait_group 0;" ::: "memory");
    storeB(0);
    __syncthreads();

    for (int it = 0; it < NITER; ++it) {
        const int s = it & 1;
        if (it + 1 < NITER) {
            issueA(it + 1, s ^ 1);
            loadB(it + 1);
        }
        compute(s);
        if (it + 1 < NITER) {
            asm volatile("cp.async.wait_group 0;" ::: "memory");
            storeB(s ^ 1);
        }
        __syncthreads();
    }

    // ---------------- epilogue ----------------
#pragma unroll
    for (int mi = 0; mi < 4; mi++) {
        int r = row0 + wm * 64 + mi * 16 + gi;
        float* o0 = out + (size_t)r * O_DIM + col0 + wn * 32;
        float* o1 = o0 + 8 * O_DIM;
#pragma unroll
        for (int nb = 0; nb < 4; nb++) {
            int c = nb * 8 + 2 * tq;
            *reinterpret_cast<float2*>(o0 + c) = make_float2(acc[mi][nb][0], acc[mi][nb][1]);
            *reinterpret_cast<float2*>(o1 + c) = make_float2(acc[mi][nb][2], acc[mi][nb][3]);
        }
    }
}

extern "C" void kernel_launch(void* const* d_in, const int* in_sizes, int n_in,
                              void* d_out, int out_size) {
    const float* x       = (const float*)d_in[0];
    const int*   qweight = (const int*)d_in[1];
    const float* scales  = (const float*)d_in[2];
    const int*   qzeros  = (const int*)d_in[3];
    float*       out     = (float*)d_out;

    static int configured = 0;
    if (!configured) {
        cudaFuncSetAttribute(q4_f16_mma, cudaFuncAttributeMaxDynamicSharedMemorySize, SMEM_BYTES);
        configured = 1;
    }

    // 1) round x -> fp16 tile images (idempotent, capturable)
    round_x_kernel<<<8192, 256>>>((const float4*)x);

    // 2) GEMM
    dim3 grid(O_DIM / BN, 4096 / BM);   // (86, 32)
    q4_f16_mma<<<grid, THREADS, SMEM_BYTES>>>(qweight, scales, qzeros, out);
}

// round 12
// speedup vs baseline: 1.1178x; 1.1178x over previous
#include <cuda_runtime.h>
#include <cuda_fp16.h>
#include <cstdint>

// x:[4096,4096] f32, qweight:[4096,1376] i32 (8x int4 along O), scales:[32,11008] f32,
// qzeros:[32,1376] i32, out:[4096,11008] f32, group_size=128.
// fp16 mma.sync m16n8k16. A via cp.async image + ldmatrix. B: Marlin-style —
// qweight pre-shuffled into fragment nibble order, dequantized in registers
// (LOP3 + HSUB2 exact + HMUL2), never touching SMEM.

#define I_DIM 4096
#define O_DIM 11008
#define OPACK 1376
#define BM 128
#define BN 128
#define BK 64
#define NITER 64
#define THREADS 256

#define A_WORDS (BM * BK / 2)             // 4096 words = 16KB image
#define SMEM_BYTES (2 * A_WORDS * 4)      // 32KB (A double buffer only)

// x as fp16x2 tile images: [rt(32)][itk(64)][4096 words]
__device__ uint32_t g_xr[(size_t)32 * 64 * A_WORDS];
// qweight shuffled: [it(64)][nbg(1376)][kb2(2)][lane(32)] one uint32 each
__device__ uint32_t g_wshuf[(size_t)64 * 1376 * 2 * 32];
// per (g,n): lo16 = f16(1024+z), hi16 = f16(scale)
__device__ uint32_t g_cs[(size_t)32 * 11008];

__device__ __forceinline__ uint32_t pack_f16x2(float lo, float hi) {
    uint32_t d;
    asm("cvt.rn.f16x2.f32 %0, %1, %2;" : "=r"(d) : "f"(hi), "f"(lo));
    return d;
}

__device__ __forceinline__ uint32_t smem_u32(const void* p) {
    uint32_t a;
    asm("{ .reg .u64 t; cvta.to.shared.u64 t, %1; cvt.u32.u64 %0, t; }" : "=r"(a) : "l"(p));
    return a;
}

__device__ __forceinline__ void cp_async16(uint32_t dst, const void* src) {
    asm volatile("cp.async.cg.shared.global [%0], [%1], 16;" :: "r"(dst), "l"(src) : "memory");
}

__device__ __forceinline__ void ldmatrix_x4(uint32_t* r, uint32_t addr) {
    asm volatile("ldmatrix.sync.aligned.m8n8.x4.shared.b16 {%0,%1,%2,%3}, [%4];"
                 : "=r"(r[0]), "=r"(r[1]), "=r"(r[2]), "=r"(r[3]) : "r"(addr));
}

__device__ __forceinline__ void mma_f16(float* d, const uint32_t* a, const uint32_t* b) {
    asm volatile(
        "mma.sync.aligned.m16n8k16.row.col.f32.f16.f16.f32 "
        "{%0,%1,%2,%3},{%4,%5,%6,%7},{%8,%9},{%0,%1,%2,%3};"
        : "+f"(d[0]), "+f"(d[1]), "+f"(d[2]), "+f"(d[3])
        : "r"(a[0]), "r"(a[1]), "r"(a[2]), "r"(a[3]), "r"(b[0]), "r"(b[1]));
}

__device__ __forceinline__ uint32_t hsub2(uint32_t a, uint32_t b) {
    uint32_t d; asm("sub.rn.f16x2 %0, %1, %2;" : "=r"(d) : "r"(a), "r"(b)); return d;
}
__device__ __forceinline__ uint32_t hmul2(uint32_t a, uint32_t b) {
    uint32_t d; asm("mul.rn.f16x2 %0, %1, %2;" : "=r"(d) : "r"(a), "r"(b)); return d;
}
__device__ __forceinline__ uint32_t prmt(uint32_t a, uint32_t sel) {
    uint32_t d; asm("prmt.b32 %0, %1, %1, %2;" : "=r"(d) : "r"(a), "r"(sel)); return d;
}

// ---- pre-kernel 1: x -> fp16 tile images (layout identical to R11) ----
__global__ __launch_bounds__(256)
void round_x_kernel(const float4* __restrict__ x) {
    size_t idx = (size_t)blockIdx.x * 256 + threadIdx.x;
    int r  = (int)(idx >> 9);
    int cg = (int)(idx & 511);
    float4 v0 = x[idx * 2];
    float4 v1 = x[idx * 2 + 1];
    uint4 u;
    u.x = pack_f16x2(v0.x, v0.y);
    u.y = pack_f16x2(v0.z, v0.w);
    u.z = pack_f16x2(v1.x, v1.y);
    u.w = pack_f16x2(v1.z, v1.w);
    int rt = r >> 7, rl = r & 127;
    int itk = cg >> 3, c = cg & 7;
    int ta = ((rl >> 1) & 3) | ((rl & 1) << 2);
    *reinterpret_cast<uint4*>(
        g_xr + (((size_t)rt * 64 + itk) << 12) + rl * 32 + ((c ^ ta) << 2)) = u;
}

// ---- pre-kernel 2: qweight -> fragment-ordered nibbles ----
// out word (it, nbg, kb2, lane): 8 nibbles for n = nbg*8 + (lane>>2),
// k = it*64 + kb2*32 + {2tq,2tq+1, 8+2tq,8+2tq+1, 16+2tq,16+2tq+1, 24+2tq,24+2tq+1}
// packed at shifts {0,16, 4,20, 8,24, 12,28} so that ((w>>8*sel)&0x000F000F)
// and ((w>>(4+8*sel))&0x000F000F) yield the b0/b1 f16x2 pairs for k16-block sel.
__global__ __launch_bounds__(256)
void shuffle_w_kernel(const int* __restrict__ qw) {
    size_t o = (size_t)blockIdx.x * 256 + threadIdx.x;   // < 5,636,096
    int lane = (int)(o & 31);
    size_t r = o >> 5;
    int kb2 = (int)(r & 1); r >>= 1;
    int nbg = (int)(r % 1376);
    int it  = (int)(r / 1376);
    int gi = lane >> 2, tq = lane & 3;
    int base = it * 64 + kb2 * 32 + 2 * tq;
    uint32_t w = 0;
    const int ks[8]     = {base, base + 1, base + 8, base + 9,
                           base + 16, base + 17, base + 24, base + 25};
    const int shifts[8] = {0, 16, 4, 20, 8, 24, 12, 28};
#pragma unroll
    for (int j = 0; j < 8; j++) {
        uint32_t nib = ((uint32_t)qw[(size_t)ks[j] * OPACK + nbg] >> (4 * gi)) & 0xF;
        w |= nib << shifts[j];
    }
    g_wshuf[o] = w;
}

// ---- pre-kernel 3: per (g,n) pack {f16(1024+z), f16(scale)} ----
__global__ __launch_bounds__(256)
void build_cs_kernel(const float* __restrict__ scales, const int* __restrict__ qz) {
    int i = blockIdx.x * 256 + threadIdx.x;   // < 32*11008
    int g = i / O_DIM, n = i % O_DIM;
    int z = (qz[(size_t)g * OPACK + (n >> 3)] >> (4 * (n & 7))) & 0xF;
    uint32_t hs = __half_as_ushort(__float2half(scales[i]));
    uint32_t hz = __half_as_ushort(__float2half(1024.0f + (float)z));
    g_cs[i] = (hs << 16) | hz;
}

// ---- main GEMM ----
__global__ __launch_bounds__(THREADS, 2)
void q4_f16_mma(float* __restrict__ out) {
    extern __shared__ uint32_t smem[];
    const uint32_t sbase = smem_u32(smem);

    const int tid  = threadIdx.x;
    const int lane = tid & 31;
    const int wid  = tid >> 5;
    const int gi   = lane >> 2;
    const int tq   = lane & 3;

    const int row0 = blockIdx.y * BM;
    const int col0 = blockIdx.x * BN;

    // 8 warps: 2 (M, 64) x 4 (N, 32)
    const int wm = wid & 1;
    const int wn = wid >> 1;

    // A ldmatrix lane roles (identical to R11 — proven)
    const int lj = lane & 7;
    const int lg = lane >> 3;
    const int ta_l = ((lj >> 1) & 3) | ((lj & 1) << 2);
    const int a_csel = lg >> 1;
    uint32_t a_row_byte[4];
#pragma unroll
    for (int mi = 0; mi < 4; mi++)
        a_row_byte[mi] = (uint32_t)(wm * 64 + mi * 16 + ((lg & 1) << 3) + lj) * 128;

    const uint32_t* a_img = g_xr + (((size_t)(row0 >> 7)) * 64 << 12);

    // B pointers: nbg0 = global n-oct base for this warp
    const int nbg0 = (col0 >> 3) + wn * 4;
    const uint32_t* wp0 = g_wshuf + ((size_t)nbg0 * 2) * 32 + lane;
    const uint32_t* csp = g_cs + col0 + wn * 32 + gi;   // + g*O_DIM + nb*8

    uint32_t wcur[8], wnext[8];
    uint32_t hz2[4], s2[4], cnext[4];

    float acc[4][4][4];
#pragma unroll
    for (int mi = 0; mi < 4; mi++)
#pragma unroll
        for (int nb = 0; nb < 4; nb++)
#pragma unroll
            for (int j = 0; j < 4; j++) acc[mi][nb][j] = 0.0f;

    auto issueA = [&](int it, int stage) {
        const uint32_t aB = sbase + stage * (A_WORDS * 4);
        const uint32_t* src = a_img + ((size_t)it << 12);
#pragma unroll
        for (int j = 0; j < 4; j++) {
            int c = tid + j * 256;
            cp_async16(aB + c * 16, src + c * 4);
        }
        asm volatile("cp.async.commit_group;" ::: "memory");
    };

    auto loadBw = [&](int it, uint32_t* dst) {
        const uint32_t* p = wp0 + (size_t)it * (1376 * 2 * 32);
#pragma unroll
        for (int nb = 0; nb < 4; nb++)
#pragma unroll
            for (int kb2 = 0; kb2 < 2; kb2++)
                dst[nb * 2 + kb2] = p[(nb * 2 + kb2) * 32];
    };

    auto loadCS = [&](int g, uint32_t* dst) {
#pragma unroll
        for (int nb = 0; nb < 4; nb++)
            dst[nb] = csp[(size_t)g * O_DIM + nb * 8];
    };

    auto applyCS = [&](const uint32_t* c) {
#pragma unroll
        for (int nb = 0; nb < 4; nb++) {
            hz2[nb] = prmt(c[nb], 0x1010);
            s2[nb]  = prmt(c[nb], 0x3232);
        }
    };

    auto compute = [&](int stage) {
        const uint32_t aB = sbase + stage * (A_WORDS * 4);
#pragma unroll
        for (int kb = 0; kb < 4; kb++) {
            uint32_t a[4][4];
#pragma unroll
            for (int mi = 0; mi < 4; mi++)
                ldmatrix_x4(a[mi], aB + a_row_byte[mi]
                            + ((uint32_t)((2 * kb + a_csel) ^ ta_l) << 4));
#pragma unroll
            for (int nb = 0; nb < 4; nb++) {
                uint32_t w = wcur[nb * 2 + (kb >> 1)];
                uint32_t t = (kb & 1) ? (w >> 8) : w;
                uint32_t v0 = (t & 0x000F000Fu) | 0x64006400u;
                uint32_t v1 = ((t >> 4) & 0x000F000Fu) | 0x64006400u;
                uint32_t b[2];
                b[0] = hmul2(hsub2(v0, hz2[nb]), s2[nb]);
                b[1] = hmul2(hsub2(v1, hz2[nb]), s2[nb]);
#pragma unroll
                for (int mi = 0; mi < 4; mi++)
                    mma_f16(acc[mi][nb], a[mi], b);
            }
        }
    };

    // ---------------- pipeline ----------------
    issueA(0, 0);
    loadBw(0, wcur);
    {
        uint32_t c0[4];
        loadCS(0, c0);
        applyCS(c0);
    }
    asm volatile("cp.async.wait_group 0;" ::: "memory");
    __syncthreads();

    for (int it = 0; it < NITER; ++it) {
        const int s = it & 1;
        if (it + 1 < NITER) {
            issueA(it + 1, s ^ 1);
            loadBw(it + 1, wnext);
            if (s == 1) loadCS((it + 1) >> 1, cnext);   // next iter starts a new group
        }
        compute(s);
        if (it + 1 < NITER) {
            asm volatile("cp.async.wait_group 0;" ::: "memory");
            __syncthreads();
#pragma unroll
            for (int j = 0; j < 8; j++) wcur[j] = wnext[j];
            if (s == 1) applyCS(cnext);
        }
    }

    // ---------------- epilogue ----------------
#pragma unroll
    for (int mi = 0; mi < 4; mi++) {
        int r = row0 + wm * 64 + mi * 16 + gi;
        float* o0 = out + (size_t)r * O_DIM + col0 + wn * 32;
        float* o1 = o0 + 8 * O_DIM;
#pragma unroll
        for (int nb = 0; nb < 4; nb++) {
            int c = nb * 8 + 2 * tq;
            *reinterpret_cast<float2*>(o0 + c) = make_float2(acc[mi][nb][0], acc[mi][nb][1]);
            *reinterpret_cast<float2*>(o1 + c) = make_float2(acc[mi][nb][2], acc[mi][nb][3]);
        }
    }
}

extern "C" void kernel_launch(void* const* d_in, const int* in_sizes, int n_in,
                              void* d_out, int out_size) {
    const float* x       = (const float*)d_in[0];
    const int*   qweight = (const int*)d_in[1];
    const float* scales  = (const float*)d_in[2];
    const int*   qzeros  = (const int*)d_in[3];
    float*       out     = (float*)d_out;

    static int configured = 0;
    if (!configured) {
        cudaFuncSetAttribute(q4_f16_mma, cudaFuncAttributeMaxDynamicSharedMemorySize, SMEM_BYTES);
        configured = 1;
    }

    // pre-passes (all idempotent, graph-capturable)
    round_x_kernel<<<8192, 256>>>((const float4*)x);
    shuffle_w_kernel<<<22016, 256>>>(qweight);
    build_cs_kernel<<<1376, 256>>>(scales, qzeros);

    dim3 grid(O_DIM / BN, 4096 / BM);   // (86, 32)
    q4_f16_mma<<<grid, THREADS, SMEM_BYTES>>>(out);
}

// round 13
// speedup vs baseline: 1.1755x; 1.0517x over previous
#include <cuda_runtime.h>
#include <cuda_fp16.h>
#include <cstdint>

// x:[4096,4096] f32, qweight:[4096,1376] i32 (8x int4 along O), scales:[32,11008] f32,
// qzeros:[32,1376] i32, out:[4096,11008] f32, group_size=128.
// fp16 mma.sync m16n8k16. A via 3-stage cp.async image pipeline + ldmatrix.
// B: register-dequant from pre-shuffled fragment-order nibbles (no B SMEM).

#define I_DIM 4096
#define O_DIM 11008
#define OPACK 1376
#define BM 128
#define BN 128
#define BK 64
#define NITER 64
#define THREADS 256
#define STAGES 3

#define A_WORDS (BM * BK / 2)             // 4096 words = 16KB image
#define SMEM_BYTES (STAGES * A_WORDS * 4) // 48KB

__device__ uint32_t g_xr[(size_t)32 * 64 * A_WORDS];
__device__ uint32_t g_wshuf[(size_t)64 * 1376 * 2 * 32];
__device__ uint32_t g_cs[(size_t)32 * 11008];

__device__ __forceinline__ uint32_t pack_f16x2(float lo, float hi) {
    uint32_t d;
    asm("cvt.rn.f16x2.f32 %0, %1, %2;" : "=r"(d) : "f"(hi), "f"(lo));
    return d;
}
__device__ __forceinline__ uint32_t smem_u32(const void* p) {
    uint32_t a;
    asm("{ .reg .u64 t; cvta.to.shared.u64 t, %1; cvt.u32.u64 %0, t; }" : "=r"(a) : "l"(p));
    return a;
}
__device__ __forceinline__ void cp_async16(uint32_t dst, const void* src) {
    asm volatile("cp.async.cg.shared.global [%0], [%1], 16;" :: "r"(dst), "l"(src) : "memory");
}
__device__ __forceinline__ void ldmatrix_x4(uint32_t* r, uint32_t addr) {
    asm volatile("ldmatrix.sync.aligned.m8n8.x4.shared.b16 {%0,%1,%2,%3}, [%4];"
                 : "=r"(r[0]), "=r"(r[1]), "=r"(r[2]), "=r"(r[3]) : "r"(addr));
}
__device__ __forceinline__ void mma_f16(float* d, const uint32_t* a, const uint32_t* b) {
    asm volatile(
        "mma.sync.aligned.m16n8k16.row.col.f32.f16.f16.f32 "
        "{%0,%1,%2,%3},{%4,%5,%6,%7},{%8,%9},{%0,%1,%2,%3};"
        : "+f"(d[0]), "+f"(d[1]), "+f"(d[2]), "+f"(d[3])
        : "r"(a[0]), "r"(a[1]), "r"(a[2]), "r"(a[3]), "r"(b[0]), "r"(b[1]));
}
__device__ __forceinline__ uint32_t hsub2(uint32_t a, uint32_t b) {
    uint32_t d; asm("sub.rn.f16x2 %0, %1, %2;" : "=r"(d) : "r"(a), "r"(b)); return d;
}
__device__ __forceinline__ uint32_t hmul2(uint32_t a, uint32_t b) {
    uint32_t d; asm("mul.rn.f16x2 %0, %1, %2;" : "=r"(d) : "r"(a), "r"(b)); return d;
}
__device__ __forceinline__ uint32_t prmt(uint32_t a, uint32_t sel) {
    uint32_t d; asm("prmt.b32 %0, %1, %1, %2;" : "=r"(d) : "r"(a), "r"(sel)); return d;
}

// ---- pre-kernel 1: x -> fp16 tile images ----
__global__ __launch_bounds__(256)
void round_x_kernel(const float4* __restrict__ x) {
    size_t idx = (size_t)blockIdx.x * 256 + threadIdx.x;
    int r  = (int)(idx >> 9);
    int cg = (int)(idx & 511);
    float4 v0 = x[idx * 2];
    float4 v1 = x[idx * 2 + 1];
    uint4 u;
    u.x = pack_f16x2(v0.x, v0.y);
    u.y = pack_f16x2(v0.z, v0.w);
    u.z = pack_f16x2(v1.x, v1.y);
    u.w = pack_f16x2(v1.z, v1.w);
    int rt = r >> 7, rl = r & 127;
    int itk = cg >> 3, c = cg & 7;
    int ta = ((rl >> 1) & 3) | ((rl & 1) << 2);
    *reinterpret_cast<uint4*>(
        g_xr + (((size_t)rt * 64 + itk) << 12) + rl * 32 + ((c ^ ta) << 2)) = u;
}

// ---- pre-kernel 2: qweight -> fragment-ordered nibbles (same as R12) ----
__global__ __launch_bounds__(256)
void shuffle_w_kernel(const int* __restrict__ qw) {
    size_t o = (size_t)blockIdx.x * 256 + threadIdx.x;
    int lane = (int)(o & 31);
    size_t r = o >> 5;
    int kb2 = (int)(r & 1); r >>= 1;
    int nbg = (int)(r % 1376);
    int it  = (int)(r / 1376);
    int gi = lane >> 2, tq = lane & 3;
    int base = it * 64 + kb2 * 32 + 2 * tq;
    uint32_t w = 0;
    const int ks[8]     = {base, base + 1, base + 8, base + 9,
                           base + 16, base + 17, base + 24, base + 25};
    const int shifts[8] = {0, 16, 4, 20, 8, 24, 12, 28};
#pragma unroll
    for (int j = 0; j < 8; j++) {
        uint32_t nib = ((uint32_t)qw[(size_t)ks[j] * OPACK + nbg] >> (4 * gi)) & 0xF;
        w |= nib << shifts[j];
    }
    g_wshuf[o] = w;
}

// ---- pre-kernel 3: per (g,n) pack {f16(1024+z), f16(scale)} ----
__global__ __launch_bounds__(256)
void build_cs_kernel(const float* __restrict__ scales, const int* __restrict__ qz) {
    int i = blockIdx.x * 256 + threadIdx.x;
    int g = i / O_DIM, n = i % O_DIM;
    int z = (qz[(size_t)g * OPACK + (n >> 3)] >> (4 * (n & 7))) & 0xF;
    uint32_t hs = __half_as_ushort(__float2half(scales[i]));
    uint32_t hz = __half_as_ushort(__float2half(1024.0f + (float)z));
    g_cs[i] = (hs << 16) | hz;
}

// ---- main GEMM ----
__global__ __launch_bounds__(THREADS, 2)
void q4_f16_mma(float* __restrict__ out) {
    extern __shared__ uint32_t smem[];
    const uint32_t sbase = smem_u32(smem);

    const int tid  = threadIdx.x;
    const int lane = tid & 31;
    const int wid  = tid >> 5;
    const int gi   = lane >> 2;
    const int tq   = lane & 3;

    const int row0 = blockIdx.y * BM;
    const int col0 = blockIdx.x * BN;

    const int wm = wid & 1;
    const int wn = wid >> 1;

    // A ldmatrix lane roles
    const int lj = lane & 7;
    const int lg = lane >> 3;
    const int ta_l = ((lj >> 1) & 3) | ((lj & 1) << 2);
    const int a_csel = lg >> 1;
    uint32_t a_row_byte[4];
#pragma unroll
    for (int mi = 0; mi < 4; mi++)
        a_row_byte[mi] = (uint32_t)(wm * 64 + mi * 16 + ((lg & 1) << 3) + lj) * 128;

    const uint32_t* a_img = g_xr + (((size_t)(row0 >> 7)) * 64 << 12);

    const int nbg0 = (col0 >> 3) + wn * 4;
    const uint32_t* wp0 = g_wshuf + ((size_t)nbg0 * 2) * 32 + lane;
    const uint32_t* csp = g_cs + col0 + wn * 32 + gi;

    const uint32_t sA[STAGES] = {sbase, sbase + A_WORDS * 4, sbase + 2 * A_WORDS * 4};

    uint32_t wA[8], wB[8];
    uint32_t hz2[4], s2[4], cnext[4];

    float acc[4][4][4];
#pragma unroll
    for (int mi = 0; mi < 4; mi++)
#pragma unroll
        for (int nb = 0; nb < 4; nb++)
#pragma unroll
            for (int j = 0; j < 4; j++) acc[mi][nb][j] = 0.0f;

    auto issueA = [&](int it, uint32_t aB) {
        const uint32_t* src = a_img + ((size_t)it << 12);
#pragma unroll
        for (int j = 0; j < 4; j++) {
            int c = tid + j * 256;
            cp_async16(aB + c * 16, src + c * 4);
        }
        asm volatile("cp.async.commit_group;" ::: "memory");
    };

    auto loadBw = [&](int it, uint32_t* dst) {
        const uint32_t* p = wp0 + (size_t)it * (1376 * 2 * 32);
#pragma unroll
        for (int j = 0; j < 8; j++) dst[j] = p[j * 32];
    };

    auto loadCS = [&](int g, uint32_t* dst) {
#pragma unroll
        for (int nb = 0; nb < 4; nb++)
            dst[nb] = csp[(size_t)g * O_DIM + nb * 8];
    };

    auto applyCS = [&](const uint32_t* c) {
#pragma unroll
        for (int nb = 0; nb < 4; nb++) {
            hz2[nb] = prmt(c[nb], 0x1010);
            s2[nb]  = prmt(c[nb], 0x3232);
        }
    };

    auto compute = [&](uint32_t aB, const uint32_t* w) {
#pragma unroll
        for (int kb = 0; kb < 4; kb++) {
            // 1) batch fragment loads
            uint32_t a[4][4];
#pragma unroll
            for (int mi = 0; mi < 4; mi++)
                ldmatrix_x4(a[mi], aB + a_row_byte[mi]
                            + ((uint32_t)((2 * kb + a_csel) ^ ta_l) << 4));
            // 2) batch dequant (hides LDS latency)
            uint32_t b[4][2];
#pragma unroll
            for (int nb = 0; nb < 4; nb++) {
                uint32_t ww = w[nb * 2 + (kb >> 1)];
                uint32_t t = (kb & 1) ? (ww >> 8) : ww;
                uint32_t v0 = (t & 0x000F000Fu) | 0x64006400u;
                uint32_t v1 = ((t >> 4) & 0x000F000Fu) | 0x64006400u;
                b[nb][0] = hmul2(hsub2(v0, hz2[nb]), s2[nb]);
                b[nb][1] = hmul2(hsub2(v1, hz2[nb]), s2[nb]);
            }
            // 3) batch MMAs
#pragma unroll
            for (int mi = 0; mi < 4; mi++)
#pragma unroll
                for (int nb = 0; nb < 4; nb++)
                    mma_f16(acc[mi][nb], a[mi], b[nb]);
        }
    };

    // ---------------- prologue ----------------
    issueA(0, sA[0]);
    issueA(1, sA[1]);
    loadBw(0, wA);
    {
        uint32_t c0[4];
        loadCS(0, c0);
        applyCS(c0);
    }
    asm volatile("cp.async.wait_group 1;" ::: "memory");   // stage0 ready
    __syncthreads();

    // ---------------- main loop (2x unrolled) ----------------
    for (int it = 0; it < NITER; it += 2) {
        // ---- even sub-iter: consumes wA, stage it%3 ----
        loadBw(it + 1, wB);
        {
            int gn = (it >> 1) + 1;
            if (gn > 31) gn = 31;
            loadCS(gn, cnext);
        }
        compute(sA[it % 3], wA);
        if (it + 2 < NITER) {
            issueA(it + 2, sA[(it + 2) % 3]);
            asm volatile("cp.async.wait_group 1;" ::: "memory");
        } else {
            asm volatile("cp.async.wait_group 0;" ::: "memory");
        }
        __syncthreads();

        // ---- odd sub-iter: consumes wB, stage (it+1)%3 ----
        if (it + 2 < NITER) loadBw(it + 2, wA);
        compute(sA[(it + 1) % 3], wB);
        applyCS(cnext);
        if (it + 3 < NITER) {
            issueA(it + 3, sA[(it + 3) % 3]);
            asm volatile("cp.async.wait_group 1;" ::: "memory");
        } else {
            asm volatile("cp.async.wait_group 0;" ::: "memory");
        }
        __syncthreads();
    }

    // ---------------- epilogue ----------------
#pragma unroll
    for (int mi = 0; mi < 4; mi++) {
        int r = row0 + wm * 64 + mi * 16 + gi;
        float* o0 = out + (size_t)r * O_DIM + col0 + wn * 32;
        float* o1 = o0 + 8 * O_DIM;
#pragma unroll
        for (int nb = 0; nb < 4; nb++) {
            int c = nb * 8 + 2 * tq;
            *reinterpret_cast<float2*>(o0 + c) = make_float2(acc[mi][nb][0], acc[mi][nb][1]);
            *reinterpret_cast<float2*>(o1 + c) = make_float2(acc[mi][nb][2], acc[mi][nb][3]);
        }
    }
}

extern "C" void kernel_launch(void* const* d_in, const int* in_sizes, int n_in,
                              void* d_out, int out_size) {
    const float* x       = (const float*)d_in[0];
    const int*   qweight = (const int*)d_in[1];
    const float* scales  = (const float*)d_in[2];
    const int*   qzeros  = (const int*)d_in[3];
    float*       out     = (float*)d_out;

    static int configured = 0;
    if (!configured) {
        cudaFuncSetAttribute(q4_f16_mma, cudaFuncAttributeMaxDynamicSharedMemorySize, SMEM_BYTES);
        configured = 1;
    }

    round_x_kernel<<<8192, 256>>>((const float4*)x);
    shuffle_w_kernel<<<22016, 256>>>(qweight);
    build_cs_kernel<<<1376, 256>>>(scales, qzeros);

    dim3 grid(O_DIM / BN, 4096 / BM);   // (86, 32)
    q4_f16_mma<<<grid, THREADS, SMEM_BYTES>>>(out);
}

// round 14
// speedup vs baseline: 1.1822x; 1.0056x over previous
#include <cuda_runtime.h>
#include <cuda_fp16.h>
#include <cstdint>

// x:[4096,4096] f32, qweight:[4096,1376] i32 (8x int4 along O), scales:[32,11008] f32,
// qzeros:[32,1376] i32, out:[4096,11008] f32, group_size=128.
// fp16 mma.sync m16n8k16. A via 4-stage cp.async image pipeline (issued 3 ahead)
// + ldmatrix. B: register-dequant from pre-shuffled fragment-order nibbles.

#define I_DIM 4096
#define O_DIM 11008
#define OPACK 1376
#define BM 128
#define BN 128
#define BK 64
#define NITER 64
#define THREADS 256
#define STAGES 4

#define A_WORDS (BM * BK / 2)             // 4096 words = 16KB image
#define SMEM_BYTES (STAGES * A_WORDS * 4) // 64KB

__device__ uint32_t g_xr[(size_t)32 * 64 * A_WORDS];
__device__ uint32_t g_wshuf[(size_t)64 * 1376 * 2 * 32];
__device__ uint32_t g_cs[(size_t)32 * 11008];

__device__ __forceinline__ uint32_t pack_f16x2(float lo, float hi) {
    uint32_t d;
    asm("cvt.rn.f16x2.f32 %0, %1, %2;" : "=r"(d) : "f"(hi), "f"(lo));
    return d;
}
__device__ __forceinline__ uint32_t smem_u32(const void* p) {
    uint32_t a;
    asm("{ .reg .u64 t; cvta.to.shared.u64 t, %1; cvt.u32.u64 %0, t; }" : "=r"(a) : "l"(p));
    return a;
}
__device__ __forceinline__ void cp_async16(uint32_t dst, const void* src) {
    asm volatile("cp.async.cg.shared.global [%0], [%1], 16;" :: "r"(dst), "l"(src) : "memory");
}
__device__ __forceinline__ void ldmatrix_x4(uint32_t* r, uint32_t addr) {
    asm volatile("ldmatrix.sync.aligned.m8n8.x4.shared.b16 {%0,%1,%2,%3}, [%4];"
                 : "=r"(r[0]), "=r"(r[1]), "=r"(r[2]), "=r"(r[3]) : "r"(addr));
}
__device__ __forceinline__ void mma_f16(float* d, const uint32_t* a, const uint32_t* b) {
    asm volatile(
        "mma.sync.aligned.m16n8k16.row.col.f32.f16.f16.f32 "
        "{%0,%1,%2,%3},{%4,%5,%6,%7},{%8,%9},{%0,%1,%2,%3};"
        : "+f"(d[0]), "+f"(d[1]), "+f"(d[2]), "+f"(d[3])
        : "r"(a[0]), "r"(a[1]), "r"(a[2]), "r"(a[3]), "r"(b[0]), "r"(b[1]));
}
__device__ __forceinline__ uint32_t hsub2(uint32_t a, uint32_t b) {
    uint32_t d; asm("sub.rn.f16x2 %0, %1, %2;" : "=r"(d) : "r"(a), "r"(b)); return d;
}
__device__ __forceinline__ uint32_t hmul2(uint32_t a, uint32_t b) {
    uint32_t d; asm("mul.rn.f16x2 %0, %1, %2;" : "=r"(d) : "r"(a), "r"(b)); return d;
}
__device__ __forceinline__ uint32_t prmt(uint32_t a, uint32_t sel) {
    uint32_t d; asm("prmt.b32 %0, %1, %1, %2;" : "=r"(d) : "r"(a), "r"(sel)); return d;
}

// ---- pre-kernel 1: x -> fp16 tile images ----
__global__ __launch_bounds__(256)
void round_x_kernel(const float4* __restrict__ x) {
    size_t idx = (size_t)blockIdx.x * 256 + threadIdx.x;
    int r  = (int)(idx >> 9);
    int cg = (int)(idx & 511);
    float4 v0 = x[idx * 2];
    float4 v1 = x[idx * 2 + 1];
    uint4 u;
    u.x = pack_f16x2(v0.x, v0.y);
    u.y = pack_f16x2(v0.z, v0.w);
    u.z = pack_f16x2(v1.x, v1.y);
    u.w = pack_f16x2(v1.z, v1.w);
    int rt = r >> 7, rl = r & 127;
    int itk = cg >> 3, c = cg & 7;
    int ta = ((rl >> 1) & 3) | ((rl & 1) << 2);
    *reinterpret_cast<uint4*>(
        g_xr + (((size_t)rt * 64 + itk) << 12) + rl * 32 + ((c ^ ta) << 2)) = u;
}

// ---- pre-kernel 2: qweight -> fragment-ordered nibbles ----
__global__ __launch_bounds__(256)
void shuffle_w_kernel(const int* __restrict__ qw) {
    size_t o = (size_t)blockIdx.x * 256 + threadIdx.x;
    int lane = (int)(o & 31);
    size_t r = o >> 5;
    int kb2 = (int)(r & 1); r >>= 1;
    int nbg = (int)(r % 1376);
    int it  = (int)(r / 1376);
    int gi = lane >> 2, tq = lane & 3;
    int base = it * 64 + kb2 * 32 + 2 * tq;
    uint32_t w = 0;
    const int ks[8]     = {base, base + 1, base + 8, base + 9,
                           base + 16, base + 17, base + 24, base + 25};
    const int shifts[8] = {0, 16, 4, 20, 8, 24, 12, 28};
#pragma unroll
    for (int j = 0; j < 8; j++) {
        uint32_t nib = ((uint32_t)qw[(size_t)ks[j] * OPACK + nbg] >> (4 * gi)) & 0xF;
        w |= nib << shifts[j];
    }
    g_wshuf[o] = w;
}

// ---- pre-kernel 3: per (g,n) pack {f16(1024+z), f16(scale)} ----
__global__ __launch_bounds__(256)
void build_cs_kernel(const float* __restrict__ scales, const int* __restrict__ qz) {
    int i = blockIdx.x * 256 + threadIdx.x;
    int g = i / O_DIM, n = i % O_DIM;
    int z = (qz[(size_t)g * OPACK + (n >> 3)] >> (4 * (n & 7))) & 0xF;
    uint32_t hs = __half_as_ushort(__float2half(scales[i]));
    uint32_t hz = __half_as_ushort(__float2half(1024.0f + (float)z));
    g_cs[i] = (hs << 16) | hz;
}

// ---- main GEMM ----
__global__ __launch_bounds__(THREADS, 2)
void q4_f16_mma(float* __restrict__ out) {
    extern __shared__ uint32_t smem[];
    const uint32_t sbase = smem_u32(smem);

    const int tid  = threadIdx.x;
    const int lane = tid & 31;
    const int wid  = tid >> 5;
    const int gi   = lane >> 2;
    const int tq   = lane & 3;

    const int row0 = blockIdx.y * BM;
    const int col0 = blockIdx.x * BN;

    const int wm = wid & 1;
    const int wn = wid >> 1;

    // A ldmatrix lane roles
    const int lj = lane & 7;
    const int lg = lane >> 3;
    const int ta_l = ((lj >> 1) & 3) | ((lj & 1) << 2);
    const int a_csel = lg >> 1;
    uint32_t a_row_byte[4];
#pragma unroll
    for (int mi = 0; mi < 4; mi++)
        a_row_byte[mi] = (uint32_t)(wm * 64 + mi * 16 + ((lg & 1) << 3) + lj) * 128;

    const uint32_t* a_img = g_xr + (((size_t)(row0 >> 7)) * 64 << 12);

    const int nbg0 = (col0 >> 3) + wn * 4;
    const uint32_t* wp0 = g_wshuf + ((size_t)nbg0 * 2) * 32 + lane;
    const uint32_t* csp = g_cs + col0 + wn * 32 + gi;

    uint32_t sA[STAGES];
#pragma unroll
    for (int s = 0; s < STAGES; s++) sA[s] = sbase + s * (A_WORDS * 4);

    uint32_t wA[8], wB[8];
    uint32_t hz2[4], s2[4], cnext[4];

    float acc[4][4][4];
#pragma unroll
    for (int mi = 0; mi < 4; mi++)
#pragma unroll
        for (int nb = 0; nb < 4; nb++)
#pragma unroll
            for (int j = 0; j < 4; j++) acc[mi][nb][j] = 0.0f;

    auto issueA = [&](int it, uint32_t aB) {
        const uint32_t* src = a_img + ((size_t)it << 12);
#pragma unroll
        for (int j = 0; j < 4; j++) {
            int c = tid + j * 256;
            cp_async16(aB + c * 16, src + c * 4);
        }
        asm volatile("cp.async.commit_group;" ::: "memory");
    };

    auto loadBw = [&](int it, uint32_t* dst) {
        const uint32_t* p = wp0 + (size_t)it * (1376 * 2 * 32);
#pragma unroll
        for (int j = 0; j < 8; j++) dst[j] = p[j * 32];
    };

    auto loadCS = [&](int g, uint32_t* dst) {
#pragma unroll
        for (int nb = 0; nb < 4; nb++)
            dst[nb] = csp[(size_t)g * O_DIM + nb * 8];
    };

    auto applyCS = [&](const uint32_t* c) {
#pragma unroll
        for (int nb = 0; nb < 4; nb++) {
            hz2[nb] = prmt(c[nb], 0x1010);
            s2[nb]  = prmt(c[nb], 0x3232);
        }
    };

    auto compute = [&](uint32_t aB, const uint32_t* w) {
#pragma unroll
        for (int kb = 0; kb < 4; kb++) {
            uint32_t a[4][4];
#pragma unroll
            for (int mi = 0; mi < 4; mi++)
                ldmatrix_x4(a[mi], aB + a_row_byte[mi]
                            + ((uint32_t)((2 * kb + a_csel) ^ ta_l) << 4));
            uint32_t b[4][2];
#pragma unroll
            for (int nb = 0; nb < 4; nb++) {
                uint32_t ww = w[nb * 2 + (kb >> 1)];
                uint32_t t = (kb & 1) ? (ww >> 8) : ww;
                uint32_t v0 = (t & 0x000F000Fu) | 0x64006400u;
                uint32_t v1 = ((t >> 4) & 0x000F000Fu) | 0x64006400u;
                b[nb][0] = hmul2(hsub2(v0, hz2[nb]), s2[nb]);
                b[nb][1] = hmul2(hsub2(v1, hz2[nb]), s2[nb]);
            }
#pragma unroll
            for (int mi = 0; mi < 4; mi++)
#pragma unroll
                for (int nb = 0; nb < 4; nb++)
                    mma_f16(acc[mi][nb], a[mi], b[nb]);
        }
    };

    // ---------------- prologue: 3 stages in flight ----------------
    issueA(0, sA[0]);
    issueA(1, sA[1]);
    issueA(2, sA[2]);
    loadBw(0, wA);
    {
        uint32_t c0[4];
        loadCS(0, c0);
        applyCS(c0);
    }

    // ---------------- main loop (2x unrolled, 1 wait+sync per sub-iter) ----
    for (int it = 0; it < NITER; it += 2) {
        // ---- even sub-iter: stage it%4, weights wA ----
        asm volatile("cp.async.wait_group 2;" ::: "memory");
        __syncthreads();
        if (it + 3 < NITER) issueA(it + 3, sA[(it + 3) % STAGES]);
        loadBw(it + 1, wB);
        {
            int gn = (it >> 1) + 1;
            if (gn > 31) gn = 31;
            loadCS(gn, cnext);
        }
        compute(sA[it % STAGES], wA);

        // ---- odd sub-iter: stage (it+1)%4, weights wB ----
        asm volatile("cp.async.wait_group 2;" ::: "memory");
        __syncthreads();
        if (it + 4 < NITER) issueA(it + 4, sA[(it + 4) % STAGES]);
        if (it + 2 < NITER) loadBw(it + 2, wA);
        compute(sA[(it + 1) % STAGES], wB);
        applyCS(cnext);
    }

    // ---------------- epilogue ----------------
#pragma unroll
    for (int mi = 0; mi < 4; mi++) {
        int r = row0 + wm * 64 + mi * 16 + gi;
        float* o0 = out + (size_t)r * O_DIM + col0 + wn * 32;
        float* o1 = o0 + 8 * O_DIM;
#pragma unroll
        for (int nb = 0; nb < 4; nb++) {
            int c = nb * 8 + 2 * tq;
            *reinterpret_cast<float2*>(o0 + c) = make_float2(acc[mi][nb][0], acc[mi][nb][1]);
            *reinterpret_cast<float2*>(o1 + c) = make_float2(acc[mi][nb][2], acc[mi][nb][3]);
        }
    }
}

extern "C" void kernel_launch(void* const* d_in, const int* in_sizes, int n_in,
                              void* d_out, int out_size) {
    const float* x       = (const float*)d_in[0];
    const int*   qweight = (const int*)d_in[1];
    const float* scales  = (const float*)d_in[2];
    const int*   qzeros  = (const int*)d_in[3];
    float*       out     = (float*)d_out;

    static int configured = 0;
    if (!configured) {
        cudaFuncSetAttribute(q4_f16_mma, cudaFuncAttributeMaxDynamicSharedMemorySize, SMEM_BYTES);
        configured = 1;
    }

    round_x_kernel<<<8192, 256>>>((const float4*)x);
    shuffle_w_kernel<<<22016, 256>>>(qweight);
    build_cs_kernel<<<1376, 256>>>(scales, qzeros);

    dim3 grid(O_DIM / BN, 4096 / BM);   // (86, 32)
    q4_f16_mma<<<grid, THREADS, SMEM_BYTES>>>(out);
}

// round 15
// speedup vs baseline: 1.1903x; 1.0069x over previous
#include <cuda_runtime.h>
#include <cuda_fp16.h>
#include <cstdint>

// x:[4096,4096] f32, qweight:[4096,1376] i32 (8x int4 along O), scales:[32,11008] f32,
// qzeros:[32,1376] i32, out:[4096,11008] f32, group_size=128.
// fp16 mma.sync m16n8k16. A via 4-stage cp.async image pipeline + ldmatrix.
// B: register-dequant; weights/scales repacked so per-iter loads are LDG.128.

#define I_DIM 4096
#define O_DIM 11008
#define OPACK 1376
#define NBGQ 344                          // O/32
#define BM 128
#define BN 128
#define BK 64
#define NITER 64
#define THREADS 256
#define STAGES 4

#define A_WORDS (BM * BK / 2)             // 4096 words = 16KB image
#define SMEM_BYTES (STAGES * A_WORDS * 4) // 64KB

__device__ uint32_t g_xr[(size_t)32 * 64 * A_WORDS];
// [it(64)][nbgq(344)][lane(32)][j(8)]  j = nb*2 + kb2
__device__ uint32_t g_wshuf[(size_t)64 * NBGQ * 32 * 8];
// [g(32)][c32(344)][gi(8)][nb(4)]  value = (f16(scale)<<16) | f16(1024+z)
__device__ uint32_t g_cs[(size_t)32 * NBGQ * 8 * 4];

__device__ __forceinline__ uint32_t pack_f16x2(float lo, float hi) {
    uint32_t d;
    asm("cvt.rn.f16x2.f32 %0, %1, %2;" : "=r"(d) : "f"(hi), "f"(lo));
    return d;
}
__device__ __forceinline__ uint32_t smem_u32(const void* p) {
    uint32_t a;
    asm("{ .reg .u64 t; cvta.to.shared.u64 t, %1; cvt.u32.u64 %0, t; }" : "=r"(a) : "l"(p));
    return a;
}
__device__ __forceinline__ void cp_async16(uint32_t dst, const void* src) {
    asm volatile("cp.async.cg.shared.global [%0], [%1], 16;" :: "r"(dst), "l"(src) : "memory");
}
__device__ __forceinline__ void ldmatrix_x4(uint32_t* r, uint32_t addr) {
    asm volatile("ldmatrix.sync.aligned.m8n8.x4.shared.b16 {%0,%1,%2,%3}, [%4];"
                 : "=r"(r[0]), "=r"(r[1]), "=r"(r[2]), "=r"(r[3]) : "r"(addr));
}
__device__ __forceinline__ void mma_f16(float* d, const uint32_t* a, const uint32_t* b) {
    asm volatile(
        "mma.sync.aligned.m16n8k16.row.col.f32.f16.f16.f32 "
        "{%0,%1,%2,%3},{%4,%5,%6,%7},{%8,%9},{%0,%1,%2,%3};"
        : "+f"(d[0]), "+f"(d[1]), "+f"(d[2]), "+f"(d[3])
        : "r"(a[0]), "r"(a[1]), "r"(a[2]), "r"(a[3]), "r"(b[0]), "r"(b[1]));
}
__device__ __forceinline__ uint32_t hsub2(uint32_t a, uint32_t b) {
    uint32_t d; asm("sub.rn.f16x2 %0, %1, %2;" : "=r"(d) : "r"(a), "r"(b)); return d;
}
__device__ __forceinline__ uint32_t hmul2(uint32_t a, uint32_t b) {
    uint32_t d; asm("mul.rn.f16x2 %0, %1, %2;" : "=r"(d) : "r"(a), "r"(b)); return d;
}
__device__ __forceinline__ uint32_t prmt(uint32_t a, uint32_t sel) {
    uint32_t d; asm("prmt.b32 %0, %1, %1, %2;" : "=r"(d) : "r"(a), "r"(sel)); return d;
}

// ---- pre-kernel 1: x -> fp16 tile images ----
__global__ __launch_bounds__(256)
void round_x_kernel(const float4* __restrict__ x) {
    size_t idx = (size_t)blockIdx.x * 256 + threadIdx.x;
    int r  = (int)(idx >> 9);
    int cg = (int)(idx & 511);
    float4 v0 = x[idx * 2];
    float4 v1 = x[idx * 2 + 1];
    uint4 u;
    u.x = pack_f16x2(v0.x, v0.y);
    u.y = pack_f16x2(v0.z, v0.w);
    u.z = pack_f16x2(v1.x, v1.y);
    u.w = pack_f16x2(v1.z, v1.w);
    int rt = r >> 7, rl = r & 127;
    int itk = cg >> 3, c = cg & 7;
    int ta = ((rl >> 1) & 3) | ((rl & 1) << 2);
    *reinterpret_cast<uint4*>(
        g_xr + (((size_t)rt * 64 + itk) << 12) + rl * 32 + ((c ^ ta) << 2)) = u;
}

// ---- pre-kernel 2: qweight -> fragment-ordered nibbles, LDG.128-friendly ----
__global__ __launch_bounds__(256)
void shuffle_w_kernel(const int* __restrict__ qw) {
    size_t o = (size_t)blockIdx.x * 256 + threadIdx.x;   // 64*344*32*8
    int j    = (int)(o & 7);          // nb*2 + kb2
    int lane = (int)((o >> 3) & 31);
    size_t r = o >> 8;
    int nbgq = (int)(r % NBGQ);
    int it   = (int)(r / NBGQ);
    int nb = j >> 1, kb2 = j & 1;
    int nbg = nbgq * 4 + nb;
    int gi = lane >> 2, tq = lane & 3;
    int base = it * 64 + kb2 * 32 + 2 * tq;
    uint32_t w = 0;
    const int ks[8]     = {base, base + 1, base + 8, base + 9,
                           base + 16, base + 17, base + 24, base + 25};
    const int shifts[8] = {0, 16, 4, 20, 8, 24, 12, 28};
#pragma unroll
    for (int t = 0; t < 8; t++) {
        uint32_t nib = ((uint32_t)qw[(size_t)ks[t] * OPACK + nbg] >> (4 * gi)) & 0xF;
        w |= nib << shifts[t];
    }
    g_wshuf[o] = w;
}

// ---- pre-kernel 3: pack {f16(1024+z), f16(scale)} per (g, c32, gi, nb) ----
__global__ __launch_bounds__(256)
void build_cs_kernel(const float* __restrict__ scales, const int* __restrict__ qz) {
    int i = blockIdx.x * 256 + threadIdx.x;   // 32*344*8*4 = 352256
    int nb  = i & 3;
    int gi  = (i >> 2) & 7;
    int c32 = (i >> 5) % NBGQ;
    int g   = (i >> 5) / NBGQ;
    int n = c32 * 32 + nb * 8 + gi;
    int z = (qz[(size_t)g * OPACK + (n >> 3)] >> (4 * (n & 7))) & 0xF;
    uint32_t hs = __half_as_ushort(__float2half(scales[(size_t)g * O_DIM + n]));
    uint32_t hz = __half_as_ushort(__float2half(1024.0f + (float)z));
    g_cs[i] = (hs << 16) | hz;
}

// ---- main GEMM ----
__global__ __launch_bounds__(THREADS, 2)
void q4_f16_mma(float* __restrict__ out) {
    extern __shared__ uint32_t smem[];
    const uint32_t sbase = smem_u32(smem);

    const int tid  = threadIdx.x;
    const int lane = tid & 31;
    const int wid  = tid >> 5;
    const int gi   = lane >> 2;
    const int tq   = lane & 3;

    const int row0 = blockIdx.y * BM;
    const int col0 = blockIdx.x * BN;

    const int wm = wid & 1;
    const int wn = wid >> 1;

    // A ldmatrix lane roles
    const int lj = lane & 7;
    const int lg = lane >> 3;
    const int ta_l = ((lj >> 1) & 3) | ((lj & 1) << 2);
    const int a_csel = lg >> 1;
    uint32_t a_row_byte[4];
#pragma unroll
    for (int mi = 0; mi < 4; mi++)
        a_row_byte[mi] = (uint32_t)(wm * 64 + mi * 16 + ((lg & 1) << 3) + lj) * 128;

    const uint32_t* a_img = g_xr + (((size_t)(row0 >> 7)) * 64 << 12);

    // packed B pointers
    const int nbgq0 = (col0 >> 5) + wn;   // c32 index for this warp
    const uint4* wpq = reinterpret_cast<const uint4*>(g_wshuf)
                     + ((size_t)nbgq0 * 32 + lane) * 2;
    const uint4* csq = reinterpret_cast<const uint4*>(g_cs) + (size_t)nbgq0 * 8 + gi;

    uint32_t sA[STAGES];
#pragma unroll
    for (int s = 0; s < STAGES; s++) sA[s] = sbase + s * (A_WORDS * 4);

    uint32_t wA[8], wB[8];
    uint32_t hz2[4], s2[4];
    uint4 cnext;

    float acc[4][4][4];
#pragma unroll
    for (int mi = 0; mi < 4; mi++)
#pragma unroll
        for (int nb = 0; nb < 4; nb++)
#pragma unroll
            for (int j = 0; j < 4; j++) acc[mi][nb][j] = 0.0f;

    auto issueA = [&](int it, uint32_t aB) {
        const uint32_t* src = a_img + ((size_t)it << 12);
#pragma unroll
        for (int j = 0; j < 4; j++) {
            int c = tid + j * 256;
            cp_async16(aB + c * 16, src + c * 4);
        }
        asm volatile("cp.async.commit_group;" ::: "memory");
    };

    auto loadBw = [&](int it, uint32_t* dst) {
        const uint4* p = wpq + (size_t)it * (NBGQ * 64);
        *reinterpret_cast<uint4*>(dst)     = p[0];
        *reinterpret_cast<uint4*>(dst + 4) = p[1];
    };

    auto loadCS = [&](int g) {
        return csq[(size_t)g * (NBGQ * 8)];
    };

    auto applyCS = [&](uint4 c) {
        uint32_t cv[4] = {c.x, c.y, c.z, c.w};
#pragma unroll
        for (int nb = 0; nb < 4; nb++) {
            hz2[nb] = prmt(cv[nb], 0x1010);
            s2[nb]  = prmt(cv[nb], 0x3232);
        }
    };

    auto compute = [&](uint32_t aB, const uint32_t* w) {
#pragma unroll
        for (int kb = 0; kb < 4; kb++) {
            uint32_t a[4][4];
#pragma unroll
            for (int mi = 0; mi < 4; mi++)
                ldmatrix_x4(a[mi], aB + a_row_byte[mi]
                            + ((uint32_t)((2 * kb + a_csel) ^ ta_l) << 4));
            uint32_t b[4][2];
#pragma unroll
            for (int nb = 0; nb < 4; nb++) {
                uint32_t ww = w[nb * 2 + (kb >> 1)];
                uint32_t t = (kb & 1) ? (ww >> 8) : ww;
                uint32_t v0 = (t & 0x000F000Fu) | 0x64006400u;
                uint32_t v1 = ((t >> 4) & 0x000F000Fu) | 0x64006400u;
                b[nb][0] = hmul2(hsub2(v0, hz2[nb]), s2[nb]);
                b[nb][1] = hmul2(hsub2(v1, hz2[nb]), s2[nb]);
            }
#pragma unroll
            for (int mi = 0; mi < 4; mi++)
#pragma unroll
                for (int nb = 0; nb < 4; nb++)
                    mma_f16(acc[mi][nb], a[mi], b[nb]);
        }
    };

    // ---------------- prologue: 3 stages in flight ----------------
    issueA(0, sA[0]);
    issueA(1, sA[1]);
    issueA(2, sA[2]);
    loadBw(0, wA);
    applyCS(loadCS(0));

    // ---------------- main loop (2x unrolled) ----------------
    for (int it = 0; it < NITER; it += 2) {
        // ---- even sub-iter: stage it%4, weights wA ----
        asm volatile("cp.async.wait_group 2;" ::: "memory");
        __syncthreads();
        if (it + 3 < NITER) issueA(it + 3, sA[(it + 3) % STAGES]);
        loadBw(it + 1, wB);
        {
            int gn = (it >> 1) + 1;
            if (gn > 31) gn = 31;
            cnext = loadCS(gn);
        }
        compute(sA[it % STAGES], wA);

        // ---- odd sub-iter: stage (it+1)%4, weights wB ----
        asm volatile("cp.async.wait_group 2;" ::: "memory");
        __syncthreads();
        if (it + 4 < NITER) issueA(it + 4, sA[(it + 4) % STAGES]);
        if (it + 2 < NITER) loadBw(it + 2, wA);
        compute(sA[(it + 1) % STAGES], wB);
        applyCS(cnext);
    }

    // ---------------- epilogue ----------------
#pragma unroll
    for (int mi = 0; mi < 4; mi++) {
        int r = row0 + wm * 64 + mi * 16 + gi;
        float* o0 = out + (size_t)r * O_DIM + col0 + wn * 32;
        float* o1 = o0 + 8 * O_DIM;
#pragma unroll
        for (int nb = 0; nb < 4; nb++) {
            int c = nb * 8 + 2 * tq;
            *reinterpret_cast<float2*>(o0 + c) = make_float2(acc[mi][nb][0], acc[mi][nb][1]);
            *reinterpret_cast<float2*>(o1 + c) = make_float2(acc[mi][nb][2], acc[mi][nb][3]);
        }
    }
}

extern "C" void kernel_launch(void* const* d_in, const int* in_sizes, int n_in,
                              void* d_out, int out_size) {
    const float* x       = (const float*)d_in[0];
    const int*   qweight = (const int*)d_in[1];
    const float* scales  = (const float*)d_in[2];
    const int*   qzeros  = (const int*)d_in[3];
    float*       out     = (float*)d_out;

    static int configured = 0;
    if (!configured) {
        cudaFuncSetAttribute(q4_f16_mma, cudaFuncAttributeMaxDynamicSharedMemorySize, SMEM_BYTES);
        configured = 1;
    }

    round_x_kernel<<<8192, 256>>>((const float4*)x);
    shuffle_w_kernel<<<22016, 256>>>(qweight);
    build_cs_kernel<<<1376, 256>>>(scales, qzeros);

    dim3 grid(O_DIM / BN, 4096 / BM);   // (86, 32)
    q4_f16_mma<<<grid, THREADS, SMEM_BYTES>>>(out);
}